// round 12
// baseline (speedup 1.0000x reference)
#include <cuda_runtime.h>
#include <cuda_fp16.h>
#include <cstdint>

// ---------------------------------------------------------------------------
// HydraLoRA: router (8 experts, top-2) + rank-32 LoRA, fp32.
// x [8192,4096], A [8,32,4096], Bw [8,4096,32], Wr [8,4096], br [8]
// out [8192,4096]
//
// sm_100 (no 'a') -> no tcgen05; tensor path = ldmatrix + mma.sync.m16n8k16
// fp16 single-pass (norm rel_err ~4e-4 << 1e-3, seed-fixed inputs).
// R12: keep R10's 4-launch structure (prep, router, compact, fused -> ncu
// 4th-launch capture hits k_fused) and 2-tok/warp router; REVERT compact to
// the R9-proven serial version (bisecting the repeated container failures).
// k_fused identical to the R9-passing version.
// ---------------------------------------------------------------------------

typedef unsigned int u32;

#define T_TOT     8192
#define DIN       4096
#define DOUT      4096
#define NE        8
#define RK        32
#define NPAIR     64
#define TILE_T    128
#define MAX_TILES 128      // worst case 8192/128 + 56 partial = 120
#define KC        64       // k-chunk (per parity group) for phase 1
#define NC        256      // n-chunk for phase 2

__device__ int   g_pairCount[NPAIR];
__device__ int   g_pairList[NPAIR * T_TOT];
__device__ float g_gate[T_TOT * 2];
__device__ int   g_tilePair[MAX_TILES];
__device__ int   g_tileOff[MAX_TILES];
__device__ int   g_tileLen[MAX_TILES];
__device__ int   g_numTiles;
__device__ __align__(16) __half g_Ah[NE * RK * DIN];
__device__ __align__(16) __half g_Bh[NE * DOUT * RK];
__device__ __align__(16) __half g_xh[T_TOT * DIN];      // x in fp16 (64 MB)

// ------------------------------- helpers -----------------------------------
__device__ __forceinline__ u32 s2u(const void* p) {
    u32 a;
    asm("{ .reg .u64 t; cvta.to.shared.u64 t, %1; cvt.u32.u64 %0, t; }"
        : "=r"(a) : "l"(p));
    return a;
}
__device__ __forceinline__ u32 swz(u32 o) { return o ^ ((o >> 3) & 0x70); }

__device__ __forceinline__ void sts128(u32 a, u32 x, u32 y, u32 z, u32 w) {
    asm volatile("st.shared.v4.b32 [%0], {%1,%2,%3,%4};"
                 :: "r"(a), "r"(x), "r"(y), "r"(z), "r"(w) : "memory");
}
__device__ __forceinline__ void sts128v(u32 a, uint4 v) { sts128(a, v.x, v.y, v.z, v.w); }
__device__ __forceinline__ void sts32(u32 a, u32 v) {
    asm volatile("st.shared.b32 [%0], %1;" :: "r"(a), "r"(v) : "memory");
}

__device__ __forceinline__ void ldsm4(u32* r, u32 addr) {
    asm volatile("ldmatrix.sync.aligned.m8n8.x4.shared.b16 {%0,%1,%2,%3}, [%4];"
                 : "=r"(r[0]), "=r"(r[1]), "=r"(r[2]), "=r"(r[3]) : "r"(addr));
}

__device__ __forceinline__ void mma16816(float* d, const u32* a, u32 b0, u32 b1) {
    asm volatile("mma.sync.aligned.m16n8k16.row.col.f32.f16.f16.f32 "
                 "{%0,%1,%2,%3}, {%4,%5,%6,%7}, {%8,%9}, {%0,%1,%2,%3};"
                 : "+f"(d[0]), "+f"(d[1]), "+f"(d[2]), "+f"(d[3])
                 : "r"(a[0]), "r"(a[1]), "r"(a[2]), "r"(a[3]), "r"(b0), "r"(b1));
}

__device__ __forceinline__ u32 f2h2(float a, float b) {
    __half2 h = __floats2half2_rn(a, b);
    return *(u32*)&h;
}

// ---------------------------------------------------------------------------
// Prep: zero pair counters + convert A and Bw to fp16. One kernel so that
// k_fused is the 4th launch (profiler capture window).
// Blocks [0,1024): A (1M elems); blocks [1024,2048): Bw (1M elems).
__global__ __launch_bounds__(256) void k_prep(
    const float* __restrict__ A, const float* __restrict__ Bw)
{
    if (blockIdx.x == 0 && threadIdx.x < NPAIR) g_pairCount[threadIdx.x] = 0;

    if (blockIdx.x < 1024) {
        int base = (blockIdx.x * 256 + threadIdx.x) * 4;
        float4 v = *(const float4*)(A + base);
        *(u32*)(g_Ah + base)     = f2h2(v.x, v.y);
        *(u32*)(g_Ah + base + 2) = f2h2(v.z, v.w);
    } else {
        int base = ((blockIdx.x - 1024) * 256 + threadIdx.x) * 4;
        float4 v = *(const float4*)(Bw + base);
        *(u32*)(g_Bh + base)     = f2h2(v.x, v.y);
        *(u32*)(g_Bh + base + 2) = f2h2(v.z, v.w);
    }
}

// ---------------------------------------------------------------------------
// Router: one warp per 2 tokens (2x occupancy vs R9); converts x -> fp16 too.
__global__ __launch_bounds__(256) void k_router(
    const float* __restrict__ x, const float* __restrict__ Wr,
    const float* __restrict__ br)
{
    int warp = threadIdx.x >> 5;
    int lane = threadIdx.x & 31;
    int t0 = (blockIdx.x * 8 + warp) * 2;

    const float4* x0  = (const float4*)(x + (size_t)t0 * DIN);
    const float4* wr4 = (const float4*)Wr;

    float acc[2][NE];
#pragma unroll
    for (int tt = 0; tt < 2; tt++)
#pragma unroll
        for (int e = 0; e < NE; e++) acc[tt][e] = 0.f;

#pragma unroll 4
    for (int it = 0; it < 32; it++) {
        int idx = lane + 32 * it;
        float4 wv[NE];
#pragma unroll
        for (int e = 0; e < NE; e++) wv[e] = __ldg(&wr4[e * 1024 + idx]);
#pragma unroll
        for (int tt = 0; tt < 2; tt++) {
            float4 xv = __ldg(&x0[tt * 1024 + idx]);
#pragma unroll
            for (int e = 0; e < NE; e++)
                acc[tt][e] += xv.x * wv[e].x + xv.y * wv[e].y
                            + xv.z * wv[e].z + xv.w * wv[e].w;
            // fp16 conversion side-channel for the GEMM kernel
            *(uint2*)(g_xh + (size_t)(t0 + tt) * DIN + idx * 4) =
                make_uint2(f2h2(xv.x, xv.y), f2h2(xv.z, xv.w));
        }
    }
#pragma unroll
    for (int tt = 0; tt < 2; tt++)
#pragma unroll
        for (int e = 0; e < NE; e++) {
            float v = acc[tt][e];
#pragma unroll
            for (int o = 16; o; o >>= 1) v += __shfl_xor_sync(0xffffffffu, v, o);
            acc[tt][e] = v;
        }

    if (lane == 0) {
#pragma unroll
        for (int tt = 0; tt < 2; tt++) {
            int t = t0 + tt;
            float l[NE];
            float m = -1e30f;
#pragma unroll
            for (int e = 0; e < NE; e++) { l[e] = acc[tt][e] + __ldg(&br[e]); m = fmaxf(m, l[e]); }
#pragma unroll
            for (int e = 0; e < NE; e++) l[e] = fminf(fmaxf(l[e] - m, -20.f), 20.f);

            int e0 = 0; float v0 = l[0];
#pragma unroll
            for (int e = 1; e < NE; e++) if (l[e] > v0) { v0 = l[e]; e0 = e; }
            int e1 = -1; float v1 = -1e30f;
#pragma unroll
            for (int e = 0; e < NE; e++) if (e != e0 && l[e] > v1) { v1 = l[e]; e1 = e; }

            float w1 = expf(v1 - v0);
            g_gate[2 * t]     = 1.f / (1.f + w1);
            g_gate[2 * t + 1] = w1 / (1.f + w1);

            int pr  = e0 * NE + e1;
            int pos = atomicAdd(&g_pairCount[pr], 1);
            g_pairList[pr * T_TOT + pos] = t;
        }
    }
}

// ---------------------------------------------------------------------------
// Compact: serial single-thread version (R9-proven).
__global__ void k_compact() {
    if (threadIdx.x == 0) {
        int nt = 0;
        for (int p = 0; p < NPAIR; p++) {
            int c = g_pairCount[p];
            for (int j = 0; j * TILE_T < c && nt < MAX_TILES; j++) {
                g_tilePair[nt] = p;
                g_tileOff[nt]  = p * T_TOT + j * TILE_T;
                int len = c - j * TILE_T;
                g_tileLen[nt]  = len < TILE_T ? len : TILE_T;
                nt++;
            }
        }
        g_numTiles = nt;
    }
}

// ---------------------------------------------------------------------------
// Fused per-tile mma.sync kernel, 512 threads (16 warps). (R9 version.)
// Phase 1: two k-parity warp groups (warps 0-7 even chunks, 8-15 odd), each
//   with m32xn32 warp tiles over its own double-buffered X/A smem; partials
//   summed through smem. Phase 2: 16 warps, n split in half per warp.
// smem layout (1024-aligned tiles, SW128 swizzled):
#define SMO_TOKS   0
#define XG_OFF(g,b) (1024 + ((g) * 2 + (b)) * 16384)         // 4 x 16KB
#define AG_OFF(g,b) (1024 + 65536 + ((g) * 2 + (b)) * 8192)  // 4 x 8KB
#define PSUM_OFF    (1024 + 65536)          // 32KB, overlays A (after phase1)
#define H_OFF       1024                    // 16KB, overlays X(0,0)
#define B2_OFF(b)   ((b) ? (1024 + 65536) : (1024 + 16384))  // 32KB each
#define SMEM_FUSED  (1024 + 65536 + 32768)  // 99328 B

__global__ __launch_bounds__(512, 1) void k_fused(float* __restrict__ out)
{
    extern __shared__ char smem[];
    const u32 sb = s2u(smem);
    int tid  = threadIdx.x;
    int wid  = tid >> 5;
    int lane = tid & 31;

    int bid = blockIdx.x;
    if (bid >= g_numTiles) return;

    int p   = g_tilePair[bid];
    int e0  = p >> 3, e1 = p & 7;
    int off = g_tileOff[bid], len = g_tileLen[bid];

    int* toks = (int*)(smem + SMO_TOKS);
    if (tid < TILE_T) toks[tid] = g_pairList[off + (tid < len ? tid : 0)];
    __syncthreads();

    // =================== phase 1: H = X * Acomb^T (K=4096) ===================
    int gsel = wid >> 3;          // k-parity group
    int w8   = wid & 7;
    int mgrp = w8 & 3, ngrp = w8 >> 2;
    int gt   = tid & 255;         // thread id within group
    int row  = gt >> 1;           // 0..127 token row (X loads)
    int half = gt & 1;            // 32-element half of the 64-wide chunk
    const __half* xrow = g_xh + (size_t)toks[row] * DIN + half * 32;

    float acc[2][4][4];
#pragma unroll
    for (int i = 0; i < 2; i++)
#pragma unroll
        for (int j = 0; j < 4; j++)
#pragma unroll
            for (int q = 0; q < 4; q++) acc[i][j][q] = 0.f;

    auto load1 = [&](int i) {
        int b  = i & 1;
        int k0 = (2 * i + gsel) * KC;
        // X: 128 rows x 64 fp16 (pre-converted), 64 B per thread
        const uint4* src = (const uint4*)(xrow + k0);
        u32 bo = row * 128 + half * 64;
#pragma unroll
        for (int q = 0; q < 4; q++)
            sts128v(sb + XG_OFF(gsel, b) + swz(bo + q * 16), __ldg(src + q));
        // A: 64 rank-rows (e0||e1) x 64 fp16
#pragma unroll
        for (int q = gt; q < 512; q += 256) {
            int rr = q >> 3, pc = q & 7;
            int e  = rr < RK ? e0 : e1;
            size_t gi = ((size_t)e * RK + (rr & 31)) * DIN + k0 + pc * 8;
            sts128v(sb + AG_OFF(gsel, b) + swz((u32)(rr * 128 + pc * 16)),
                    __ldg((const uint4*)(g_Ah + gi)));
        }
    };

    load1(0);
    for (int i = 0; i < 32; i++) {
        int b = i & 1;
        __syncthreads();
        if (i + 1 < 32) load1(i + 1);

#pragma unroll
        for (int ks = 0; ks < 4; ks++) {
            u32 xf[2][4];
#pragma unroll
            for (int mt = 0; mt < 2; mt++) {
                u32 ro = (u32)((mgrp * 32 + mt * 16 + (lane & 15)) * 128
                               + ks * 32 + (lane >> 4) * 16);
                ldsm4(xf[mt], sb + XG_OFF(gsel, b) + swz(ro));
            }
            u32 af[8];
#pragma unroll
            for (int g = 0; g < 2; g++) {
                u32 ro = (u32)((ngrp * 32 + g * 16 + ((lane >> 4) << 3) + (lane & 7)) * 128
                               + ks * 32 + ((lane >> 3) & 1) * 16);
                ldsm4(af + 4 * g, sb + AG_OFF(gsel, b) + swz(ro));
            }
#pragma unroll
            for (int mt = 0; mt < 2; mt++)
#pragma unroll
                for (int nt = 0; nt < 4; nt++)
                    mma16816(acc[mt][nt], xf[mt], af[2 * nt], af[2 * nt + 1]);
        }
    }
    __syncthreads();   // all phase-1 reads done

    // ------- epilogue: sum parity partials, gate, fp16 H to smem -------
    if (gsel == 1) {
#pragma unroll
        for (int mt = 0; mt < 2; mt++)
#pragma unroll
            for (int nt = 0; nt < 4; nt++) {
                float* d = acc[mt][nt];
                *(float4*)(smem + PSUM_OFF + w8 * 4096 + (mt * 4 + nt) * 512 + lane * 16)
                    = make_float4(d[0], d[1], d[2], d[3]);
            }
    }
    __syncthreads();
    if (gsel == 0) {
#pragma unroll
        for (int mt = 0; mt < 2; mt++) {
            int r0 = mgrp * 32 + mt * 16 + (lane >> 2);
            float ga = g_gate[2 * toks[r0] + ngrp];
            float gb = g_gate[2 * toks[r0 + 8] + ngrp];
#pragma unroll
            for (int nt = 0; nt < 4; nt++) {
                float* d = acc[mt][nt];
                float4 q = *(const float4*)(smem + PSUM_OFF + w8 * 4096
                                            + (mt * 4 + nt) * 512 + lane * 16);
                float d0 = (d[0] + q.x) * ga, d1 = (d[1] + q.y) * ga;
                float d2 = (d[2] + q.z) * gb, d3 = (d[3] + q.w) * gb;
                u32 cb = (u32)((ngrp * 32 + nt * 8 + 2 * (lane & 3)) * 2);
                sts32(sb + H_OFF + swz((u32)r0 * 128 + cb),       f2h2(d0, d1));
                sts32(sb + H_OFF + swz((u32)(r0 + 8) * 128 + cb), f2h2(d2, d3));
            }
        }
    }
    __syncthreads();

    // =================== phase 2: out = H' * Bcomb^T (K=64) ===================
    // warp w: row group (w&7)*16, n-half (w>>3) of each 256-wide n-chunk.
    int nh = wid >> 3;
    u32 Hf[4][4];
#pragma unroll
    for (int ks = 0; ks < 4; ks++) {
        u32 ro = (u32)((w8 * 16 + (lane & 15)) * 128 + ks * 32 + (lane >> 4) * 16);
        ldsm4(Hf[ks], sb + H_OFF + swz(ro));
    }

    int r0   = w8 * 16 + (lane >> 2);
    bool lv0 = r0 < len, lv1 = (r0 + 8) < len;
    size_t orow0 = (size_t)toks[r0] * DOUT;
    size_t orow1 = (size_t)toks[r0 + 8] * DOUT;

    auto load2 = [&](int c) {
        int b = c & 1, n0c = c * NC;
#pragma unroll
        for (int q = tid; q < 2048; q += 512) {
            int n = q >> 3, pc = q & 7;
            int e = pc < 4 ? e0 : e1;
            size_t gi = ((size_t)e * DOUT + n0c + n) * RK + (pc & 3) * 8;
            sts128v(sb + B2_OFF(b) + swz((u32)(n * 128 + pc * 16)),
                    __ldg((const uint4*)(g_Bh + gi)));
        }
    };

    load2(0);
    for (int c = 0; c < DOUT / NC; c++) {
        int b = c & 1;
        __syncthreads();
        if (c + 1 < DOUT / NC) load2(c + 1);

#pragma unroll
        for (int ns = 0; ns < 2; ns++) {
            int nsub = nh * 2 + ns;
            float a2[8][4];
#pragma unroll
            for (int j = 0; j < 8; j++)
#pragma unroll
                for (int q = 0; q < 4; q++) a2[j][q] = 0.f;

#pragma unroll
            for (int ks = 0; ks < 4; ks++) {
                u32 bf[16];
#pragma unroll
                for (int g = 0; g < 4; g++) {
                    u32 ro = (u32)((nsub * 64 + g * 16 + ((lane >> 4) << 3) + (lane & 7)) * 128
                                   + ks * 32 + ((lane >> 3) & 1) * 16);
                    ldsm4(bf + 4 * g, sb + B2_OFF(b) + swz(ro));
                }
#pragma unroll
                for (int nt = 0; nt < 8; nt++)
                    mma16816(a2[nt], Hf[ks], bf[2 * nt], bf[2 * nt + 1]);
            }
            size_t ob = (size_t)(c * NC + nsub * 64 + 2 * (lane & 3));
#pragma unroll
            for (int nt = 0; nt < 8; nt++) {
                if (lv0) *(float2*)(out + orow0 + ob + nt * 8) = make_float2(a2[nt][0], a2[nt][1]);
                if (lv1) *(float2*)(out + orow1 + ob + nt * 8) = make_float2(a2[nt][2], a2[nt][3]);
            }
        }
    }
}

// ---------------------------------------------------------------------------
extern "C" void kernel_launch(void* const* d_in, const int* in_sizes, int n_in,
                              void* d_out, int out_size)
{
    (void)in_sizes; (void)n_in; (void)out_size;
    const float* x  = (const float*)d_in[0];
    const float* A  = (const float*)d_in[1];
    const float* Bw = (const float*)d_in[2];
    const float* Wr = (const float*)d_in[3];
    const float* br = (const float*)d_in[4];
    float* out = (float*)d_out;

    cudaFuncSetAttribute(k_fused, cudaFuncAttributeMaxDynamicSharedMemorySize,
                         SMEM_FUSED);

    k_prep<<<2048, 256>>>(A, Bw);
    k_router<<<T_TOT / 16, 256>>>(x, Wr, br);
    k_compact<<<1, 32>>>();
    k_fused<<<MAX_TILES, 512, SMEM_FUSED>>>(out);
}

// round 13
// speedup vs baseline: 1.2827x; 1.2827x over previous
#include <cuda_runtime.h>
#include <cuda_fp16.h>
#include <cstdint>

// ---------------------------------------------------------------------------
// HydraLoRA: router (8 experts, top-2) + rank-32 LoRA, fp32.
// x [8192,4096], A [8,32,4096], Bw [8,4096,32], Wr [8,4096], br [8]
// out [8192,4096]
//
// sm_100 (no 'a') -> no tcgen05; tensor path = ldmatrix + mma.sync.m16n8k16
// fp16 single-pass (norm rel_err ~4e-4 << 1e-3, seed-fixed inputs).
// R13: k_fused loads converted to cp.async multi-stage pipelines (phase1:
// 4 stages, all 16 warps per k-chunk, no PSUM; phase2: 3 stages) — removes
// the LDG->STS long-scoreboard stalls ncu showed (tensor 16.9%, issue 12.5%).
// Router reverted to the R9-measured 4-tok/warp version.
// ---------------------------------------------------------------------------

typedef unsigned int u32;

#define T_TOT     8192
#define DIN       4096
#define DOUT      4096
#define NE        8
#define RK        32
#define NPAIR     64
#define TILE_T    128
#define MAX_TILES 128      // worst case 8192/128 + 56 partial = 120
#define KC        64       // k-chunk for phase 1 (64 chunks)
#define NC        256      // n-chunk for phase 2 (16 chunks)

__device__ int   g_pairCount[NPAIR];
__device__ int   g_pairList[NPAIR * T_TOT];
__device__ float g_gate[T_TOT * 2];
__device__ int   g_tilePair[MAX_TILES];
__device__ int   g_tileOff[MAX_TILES];
__device__ int   g_tileLen[MAX_TILES];
__device__ int   g_numTiles;
__device__ __align__(16) __half g_Ah[NE * RK * DIN];
__device__ __align__(16) __half g_Bh[NE * DOUT * RK];
__device__ __align__(16) __half g_xh[T_TOT * DIN];      // x in fp16 (64 MB)

// ------------------------------- helpers -----------------------------------
__device__ __forceinline__ u32 s2u(const void* p) {
    u32 a;
    asm("{ .reg .u64 t; cvta.to.shared.u64 t, %1; cvt.u32.u64 %0, t; }"
        : "=r"(a) : "l"(p));
    return a;
}
__device__ __forceinline__ u32 swz(u32 o) { return o ^ ((o >> 3) & 0x70); }

__device__ __forceinline__ void sts32(u32 a, u32 v) {
    asm volatile("st.shared.b32 [%0], %1;" :: "r"(a), "r"(v) : "memory");
}

__device__ __forceinline__ void cpa16(u32 dst, const void* src) {
    asm volatile("cp.async.cg.shared.global [%0], [%1], 16;"
                 :: "r"(dst), "l"(src) : "memory");
}
#define CPA_COMMIT() asm volatile("cp.async.commit_group;" ::: "memory")
#define CPA_WAIT(n)  asm volatile("cp.async.wait_group " #n ";" ::: "memory")

__device__ __forceinline__ void ldsm4(u32* r, u32 addr) {
    asm volatile("ldmatrix.sync.aligned.m8n8.x4.shared.b16 {%0,%1,%2,%3}, [%4];"
                 : "=r"(r[0]), "=r"(r[1]), "=r"(r[2]), "=r"(r[3]) : "r"(addr));
}

__device__ __forceinline__ void mma16816(float* d, const u32* a, u32 b0, u32 b1) {
    asm volatile("mma.sync.aligned.m16n8k16.row.col.f32.f16.f16.f32 "
                 "{%0,%1,%2,%3}, {%4,%5,%6,%7}, {%8,%9}, {%0,%1,%2,%3};"
                 : "+f"(d[0]), "+f"(d[1]), "+f"(d[2]), "+f"(d[3])
                 : "r"(a[0]), "r"(a[1]), "r"(a[2]), "r"(a[3]), "r"(b0), "r"(b1));
}

__device__ __forceinline__ u32 f2h2(float a, float b) {
    __half2 h = __floats2half2_rn(a, b);
    return *(u32*)&h;
}

// ---------------------------------------------------------------------------
// Prep: zero pair counters + convert A and Bw to fp16 (keeps k_fused as the
// 4th launch for the profiler). Blocks [0,1024): A; [1024,2048): Bw.
__global__ __launch_bounds__(256) void k_prep(
    const float* __restrict__ A, const float* __restrict__ Bw)
{
    if (blockIdx.x == 0 && threadIdx.x < NPAIR) g_pairCount[threadIdx.x] = 0;

    if (blockIdx.x < 1024) {
        int base = (blockIdx.x * 256 + threadIdx.x) * 4;
        float4 v = *(const float4*)(A + base);
        *(u32*)(g_Ah + base)     = f2h2(v.x, v.y);
        *(u32*)(g_Ah + base + 2) = f2h2(v.z, v.w);
    } else {
        int base = ((blockIdx.x - 1024) * 256 + threadIdx.x) * 4;
        float4 v = *(const float4*)(Bw + base);
        *(u32*)(g_Bh + base)     = f2h2(v.x, v.y);
        *(u32*)(g_Bh + base + 2) = f2h2(v.z, v.w);
    }
}

// ---------------------------------------------------------------------------
// Router: one warp per 4 tokens (R9-measured 54us); converts x -> fp16 too.
__global__ __launch_bounds__(128) void k_router(
    const float* __restrict__ x, const float* __restrict__ Wr,
    const float* __restrict__ br)
{
    int warp = threadIdx.x >> 5;
    int lane = threadIdx.x & 31;
    int t0 = (blockIdx.x * 4 + warp) * 4;

    const float4* x0  = (const float4*)(x + (size_t)t0 * DIN);
    const float4* wr4 = (const float4*)Wr;

    float acc[4][NE];
#pragma unroll
    for (int tt = 0; tt < 4; tt++)
#pragma unroll
        for (int e = 0; e < NE; e++) acc[tt][e] = 0.f;

#pragma unroll 2
    for (int it = 0; it < 32; it++) {
        int idx = lane + 32 * it;
        float4 wv[NE];
#pragma unroll
        for (int e = 0; e < NE; e++) wv[e] = __ldg(&wr4[e * 1024 + idx]);
#pragma unroll
        for (int tt = 0; tt < 4; tt++) {
            float4 xv = __ldg(&x0[tt * 1024 + idx]);
#pragma unroll
            for (int e = 0; e < NE; e++)
                acc[tt][e] += xv.x * wv[e].x + xv.y * wv[e].y
                            + xv.z * wv[e].z + xv.w * wv[e].w;
            *(uint2*)(g_xh + (size_t)(t0 + tt) * DIN + idx * 4) =
                make_uint2(f2h2(xv.x, xv.y), f2h2(xv.z, xv.w));
        }
    }
#pragma unroll
    for (int tt = 0; tt < 4; tt++)
#pragma unroll
        for (int e = 0; e < NE; e++) {
            float v = acc[tt][e];
#pragma unroll
            for (int o = 16; o; o >>= 1) v += __shfl_xor_sync(0xffffffffu, v, o);
            acc[tt][e] = v;
        }

    if (lane == 0) {
#pragma unroll
        for (int tt = 0; tt < 4; tt++) {
            int t = t0 + tt;
            float l[NE];
            float m = -1e30f;
#pragma unroll
            for (int e = 0; e < NE; e++) { l[e] = acc[tt][e] + __ldg(&br[e]); m = fmaxf(m, l[e]); }
#pragma unroll
            for (int e = 0; e < NE; e++) l[e] = fminf(fmaxf(l[e] - m, -20.f), 20.f);

            int e0 = 0; float v0 = l[0];
#pragma unroll
            for (int e = 1; e < NE; e++) if (l[e] > v0) { v0 = l[e]; e0 = e; }
            int e1 = -1; float v1 = -1e30f;
#pragma unroll
            for (int e = 0; e < NE; e++) if (e != e0 && l[e] > v1) { v1 = l[e]; e1 = e; }

            float w1 = expf(v1 - v0);
            g_gate[2 * t]     = 1.f / (1.f + w1);
            g_gate[2 * t + 1] = w1 / (1.f + w1);

            int pr  = e0 * NE + e1;
            int pos = atomicAdd(&g_pairCount[pr], 1);
            g_pairList[pr * T_TOT + pos] = t;
        }
    }
}

// ---------------------------------------------------------------------------
// Compact: serial single-thread version (R9-proven).
__global__ void k_compact() {
    if (threadIdx.x == 0) {
        int nt = 0;
        for (int p = 0; p < NPAIR; p++) {
            int c = g_pairCount[p];
            for (int j = 0; j * TILE_T < c && nt < MAX_TILES; j++) {
                g_tilePair[nt] = p;
                g_tileOff[nt]  = p * T_TOT + j * TILE_T;
                int len = c - j * TILE_T;
                g_tileLen[nt]  = len < TILE_T ? len : TILE_T;
                nt++;
            }
        }
        g_numTiles = nt;
    }
}

// ---------------------------------------------------------------------------
// Fused per-tile mma.sync kernel, 512 threads (16 warps), cp.async pipelines.
// Phase 1 (H = X*Acomb^T, K=4096): 64 chunks, 4-stage cp.async; warp tile
//   m32 x n16 (mgrp = wid&3 rows, ng2 = wid>>2 rank-16 group); no PSUM.
// Phase 2 (out = H'*Bcomb^T, K=64): 16 n-chunks of 256, 3-stage cp.async;
//   warp w: rows (w&7)*16, n-half (w>>3).
// smem: toks[128] @0; phase1 stages XS/AS 4 x 24KB @1024; H 16KB overlays
// XS(0); phase2 B stages 3 x 32KB @17408. Total 115712 B.
#define XS(s)  (1024 + (s) * 24576)
#define AS(s)  (1024 + (s) * 24576 + 16384)
#define H_OFF  1024
#define B2S(s) (17408 + (s) * 32768)
#define SMEM_FUSED 115712

__global__ __launch_bounds__(512, 1) void k_fused(float* __restrict__ out)
{
    extern __shared__ char smem[];
    const u32 sb = s2u(smem);
    int tid  = threadIdx.x;
    int wid  = tid >> 5;
    int lane = tid & 31;

    int bid = blockIdx.x;
    if (bid >= g_numTiles) return;

    int p   = g_tilePair[bid];
    int e0  = p >> 3, e1 = p & 7;
    int off = g_tileOff[bid], len = g_tileLen[bid];

    int* toks = (int*)smem;
    if (tid < TILE_T) toks[tid] = g_pairList[off + (tid < len ? tid : 0)];
    __syncthreads();

    // =================== phase 1: H = X * Acomb^T (K=4096) ===================
    int mgrp = wid & 3;           // M 32-row group
    int ng2  = wid >> 2;          // rank-16 group (0..3)

    // per-thread cp.async source/dst mapping (fixed across chunks)
    int xr = tid >> 3, xpc = tid & 7;                 // X unit j: row xr+64j
    const __half* xsrc0 = g_xh + (size_t)toks[xr] * DIN + xpc * 8;
    const __half* xsrc1 = g_xh + (size_t)toks[xr + 64] * DIN + xpc * 8;
    u32 xdst0 = swz((u32)(xr * 128 + xpc * 16));
    u32 xdst1 = swz((u32)((xr + 64) * 128 + xpc * 16));
    int ae = (xr < RK) ? e0 : e1;                     // A row = xr (0..63)
    const __half* asrc = g_Ah + ((size_t)ae * RK + (xr & 31)) * DIN + xpc * 8;
    u32 adst = swz((u32)(xr * 128 + xpc * 16));

    auto issue1 = [&](int c) {
        int s = c & 3, k0 = c * KC;
        cpa16(sb + XS(s) + xdst0, xsrc0 + k0);
        cpa16(sb + XS(s) + xdst1, xsrc1 + k0);
        cpa16(sb + AS(s) + adst,  asrc  + k0);
        CPA_COMMIT();
    };

    float acc[2][2][4];
#pragma unroll
    for (int i = 0; i < 2; i++)
#pragma unroll
        for (int j = 0; j < 2; j++)
#pragma unroll
            for (int q = 0; q < 4; q++) acc[i][j][q] = 0.f;

    issue1(0); issue1(1); issue1(2);
    for (int c = 0; c < DIN / KC; c++) {
        CPA_WAIT(2);
        __syncthreads();
        if (c + 3 < DIN / KC) issue1(c + 3);

        int s = c & 3;
#pragma unroll
        for (int ks = 0; ks < 4; ks++) {
            u32 xf[2][4];
#pragma unroll
            for (int mt = 0; mt < 2; mt++) {
                u32 ro = (u32)((mgrp * 32 + mt * 16 + (lane & 15)) * 128
                               + ks * 32 + (lane >> 4) * 16);
                ldsm4(xf[mt], sb + XS(s) + swz(ro));
            }
            u32 af[4];
            {
                u32 ro = (u32)((ng2 * 16 + ((lane >> 4) << 3) + (lane & 7)) * 128
                               + ks * 32 + ((lane >> 3) & 1) * 16);
                ldsm4(af, sb + AS(s) + swz(ro));
            }
#pragma unroll
            for (int mt = 0; mt < 2; mt++)
#pragma unroll
                for (int nt = 0; nt < 2; nt++)
                    mma16816(acc[mt][nt], xf[mt], af[2 * nt], af[2 * nt + 1]);
        }
    }
    CPA_WAIT(0);
    __syncthreads();   // all phase-1 reads/writes retired

    // ------- epilogue: gate, fp16 H to smem (no PSUM; full-K accum) -------
    int ghalf = ng2 >> 1;        // ranks <32 -> gate of e0, else e1
#pragma unroll
    for (int mt = 0; mt < 2; mt++) {
        int r0 = mgrp * 32 + mt * 16 + (lane >> 2);
        float ga = g_gate[2 * toks[r0] + ghalf];
        float gb = g_gate[2 * toks[r0 + 8] + ghalf];
#pragma unroll
        for (int nt = 0; nt < 2; nt++) {
            float* d = acc[mt][nt];
            u32 cb = (u32)((ng2 * 16 + nt * 8 + 2 * (lane & 3)) * 2);
            sts32(sb + H_OFF + swz((u32)r0 * 128 + cb),       f2h2(d[0] * ga, d[1] * ga));
            sts32(sb + H_OFF + swz((u32)(r0 + 8) * 128 + cb), f2h2(d[2] * gb, d[3] * gb));
        }
    }
    __syncthreads();

    // =================== phase 2: out = H' * Bcomb^T (K=64) ===================
    int w8 = wid & 7, nh = wid >> 3;
    u32 Hf[4][4];
#pragma unroll
    for (int ks = 0; ks < 4; ks++) {
        u32 ro = (u32)((w8 * 16 + (lane & 15)) * 128 + ks * 32 + (lane >> 4) * 16);
        ldsm4(Hf[ks], sb + H_OFF + swz(ro));
    }

    int r0   = w8 * 16 + (lane >> 2);
    bool lv0 = r0 < len, lv1 = (r0 + 8) < len;
    size_t orow0 = (size_t)toks[r0] * DOUT;
    size_t orow1 = (size_t)toks[r0 + 8] * DOUT;

    // per-thread B cp.async mapping: 4 units, n = (tid>>3)+64j, pc = tid&7
    const __half* bsrc[4];
    u32 bdst[4];
    {
        int bn = tid >> 3, bpc = tid & 7;
        int be = (bpc < 4) ? e0 : e1;
#pragma unroll
        for (int j = 0; j < 4; j++) {
            int n = bn + 64 * j;
            bsrc[j] = g_Bh + ((size_t)be * DOUT + n) * RK + (bpc & 3) * 8;
            bdst[j] = swz((u32)(n * 128 + bpc * 16));
        }
    }
    auto issue2 = [&](int c) {
        int s = c % 3;
        int koff = c * NC * RK;      // c*8192 halves
#pragma unroll
        for (int j = 0; j < 4; j++)
            cpa16(sb + B2S(s) + bdst[j], bsrc[j] + koff);
        CPA_COMMIT();
    };

    issue2(0); issue2(1);
    for (int c = 0; c < DOUT / NC; c++) {
        CPA_WAIT(1);
        __syncthreads();
        if (c + 2 < DOUT / NC) issue2(c + 2);

        int s = c % 3;
#pragma unroll
        for (int ns = 0; ns < 2; ns++) {
            int nsub = nh * 2 + ns;
            float a2[8][4];
#pragma unroll
            for (int j = 0; j < 8; j++)
#pragma unroll
                for (int q = 0; q < 4; q++) a2[j][q] = 0.f;

#pragma unroll
            for (int ks = 0; ks < 4; ks++) {
                u32 bf[16];
#pragma unroll
                for (int g = 0; g < 4; g++) {
                    u32 ro = (u32)((nsub * 64 + g * 16 + ((lane >> 4) << 3) + (lane & 7)) * 128
                                   + ks * 32 + ((lane >> 3) & 1) * 16);
                    ldsm4(bf + 4 * g, sb + B2S(s) + swz(ro));
                }
#pragma unroll
                for (int nt = 0; nt < 8; nt++)
                    mma16816(a2[nt], Hf[ks], bf[2 * nt], bf[2 * nt + 1]);
            }
            size_t ob = (size_t)(c * NC + nsub * 64 + 2 * (lane & 3));
#pragma unroll
            for (int nt = 0; nt < 8; nt++) {
                if (lv0) *(float2*)(out + orow0 + ob + nt * 8) = make_float2(a2[nt][0], a2[nt][1]);
                if (lv1) *(float2*)(out + orow1 + ob + nt * 8) = make_float2(a2[nt][2], a2[nt][3]);
            }
        }
    }
}

// ---------------------------------------------------------------------------
extern "C" void kernel_launch(void* const* d_in, const int* in_sizes, int n_in,
                              void* d_out, int out_size)
{
    (void)in_sizes; (void)n_in; (void)out_size;
    const float* x  = (const float*)d_in[0];
    const float* A  = (const float*)d_in[1];
    const float* Bw = (const float*)d_in[2];
    const float* Wr = (const float*)d_in[3];
    const float* br = (const float*)d_in[4];
    float* out = (float*)d_out;

    cudaFuncSetAttribute(k_fused, cudaFuncAttributeMaxDynamicSharedMemorySize,
                         SMEM_FUSED);

    k_prep<<<2048, 256>>>(A, Bw);
    k_router<<<T_TOT / 16, 128>>>(x, Wr, br);
    k_compact<<<1, 32>>>();
    k_fused<<<MAX_TILES, 512, SMEM_FUSED>>>(out);
}

// round 15
// speedup vs baseline: 1.3252x; 1.0331x over previous
#include <cuda_runtime.h>
#include <cuda_fp16.h>
#include <cstdint>

// ---------------------------------------------------------------------------
// HydraLoRA: router (8 experts, top-2) + rank-32 LoRA, fp32.
// x [8192,4096], A [8,32,4096], Bw [8,4096,32], Wr [8,4096], br [8]
// out [8192,4096]
//
// sm_100 (no 'a') -> no tcgen05; tensor path = ldmatrix + mma.sync.m16n8k16
// fp16 single-pass (norm rel_err ~4e-4 << 1e-3, seed-fixed inputs).
// R15 = R14 with the cp.async TAIL RACE fixed: when a pipeline stops issuing
// real groups, an EMPTY commit_group keeps the pending-group count aligned so
// wait_group N actually retires the group about to be consumed. (R14's
// rel_err 2.9e-3 came from tail chunks read before their cp.async landed.)
// Split kernels: k_h (tiles x 4 k-splits, fp32 partials) + k_out (tiles x 2
// n-splits, partial-sum + gate + phase-2 GEMM); 256 thr / <=83KB -> 2 CTA/SM.
// ---------------------------------------------------------------------------

typedef unsigned int u32;

#define T_TOT     8192
#define DIN       4096
#define DOUT      4096
#define NE        8
#define RK        32
#define NPAIR     64
#define TILE_T    128
#define MAX_TILES 128      // worst case 8192/128 + 56 partial = 120
#define KSPLIT    4
#define KC        64       // k-chunk for k_h (16 chunks per CTA)
#define NC        256      // n-chunk for k_out (8 chunks per CTA)

__device__ int   g_pairCount[NPAIR];
__device__ int   g_pairList[NPAIR * T_TOT];
__device__ float g_gate[T_TOT * 2];
__device__ int   g_tilePair[MAX_TILES];
__device__ int   g_tileOff[MAX_TILES];
__device__ int   g_tileLen[MAX_TILES];
__device__ int   g_numTiles;
__device__ __align__(16) __half g_Ah[NE * RK * DIN];
__device__ __align__(16) __half g_Bh[NE * DOUT * RK];
__device__ __align__(16) __half g_xh[T_TOT * DIN];                   // 64 MB
__device__ __align__(16) float  g_Hpart[KSPLIT * MAX_TILES * TILE_T * 64]; // 16 MB

// ------------------------------- helpers -----------------------------------
__device__ __forceinline__ u32 s2u(const void* p) {
    u32 a;
    asm("{ .reg .u64 t; cvta.to.shared.u64 t, %1; cvt.u32.u64 %0, t; }"
        : "=r"(a) : "l"(p));
    return a;
}
__device__ __forceinline__ u32 swz(u32 o) { return o ^ ((o >> 3) & 0x70); }

__device__ __forceinline__ void sts32(u32 a, u32 v) {
    asm volatile("st.shared.b32 [%0], %1;" :: "r"(a), "r"(v) : "memory");
}

__device__ __forceinline__ void cpa16(u32 dst, const void* src) {
    asm volatile("cp.async.cg.shared.global [%0], [%1], 16;"
                 :: "r"(dst), "l"(src) : "memory");
}
#define CPA_COMMIT() asm volatile("cp.async.commit_group;" ::: "memory")
#define CPA_WAIT(n)  asm volatile("cp.async.wait_group " #n ";" ::: "memory")

__device__ __forceinline__ void ldsm4(u32* r, u32 addr) {
    asm volatile("ldmatrix.sync.aligned.m8n8.x4.shared.b16 {%0,%1,%2,%3}, [%4];"
                 : "=r"(r[0]), "=r"(r[1]), "=r"(r[2]), "=r"(r[3]) : "r"(addr));
}

__device__ __forceinline__ void mma16816(float* d, const u32* a, u32 b0, u32 b1) {
    asm volatile("mma.sync.aligned.m16n8k16.row.col.f32.f16.f16.f32 "
                 "{%0,%1,%2,%3}, {%4,%5,%6,%7}, {%8,%9}, {%0,%1,%2,%3};"
                 : "+f"(d[0]), "+f"(d[1]), "+f"(d[2]), "+f"(d[3])
                 : "r"(a[0]), "r"(a[1]), "r"(a[2]), "r"(a[3]), "r"(b0), "r"(b1));
}

__device__ __forceinline__ u32 f2h2(float a, float b) {
    __half2 h = __floats2half2_rn(a, b);
    return *(u32*)&h;
}

// ---------------------------------------------------------------------------
// Prep: zero pair counters + convert A and Bw to fp16.
__global__ __launch_bounds__(256) void k_prep(
    const float* __restrict__ A, const float* __restrict__ Bw)
{
    if (blockIdx.x == 0 && threadIdx.x < NPAIR) g_pairCount[threadIdx.x] = 0;

    if (blockIdx.x < 1024) {
        int base = (blockIdx.x * 256 + threadIdx.x) * 4;
        float4 v = *(const float4*)(A + base);
        *(u32*)(g_Ah + base)     = f2h2(v.x, v.y);
        *(u32*)(g_Ah + base + 2) = f2h2(v.z, v.w);
    } else {
        int base = ((blockIdx.x - 1024) * 256 + threadIdx.x) * 4;
        float4 v = *(const float4*)(Bw + base);
        *(u32*)(g_Bh + base)     = f2h2(v.x, v.y);
        *(u32*)(g_Bh + base + 2) = f2h2(v.z, v.w);
    }
}

// ---------------------------------------------------------------------------
// Router: one warp per 4 tokens (R9-measured); converts x -> fp16 too.
__global__ __launch_bounds__(128) void k_router(
    const float* __restrict__ x, const float* __restrict__ Wr,
    const float* __restrict__ br)
{
    int warp = threadIdx.x >> 5;
    int lane = threadIdx.x & 31;
    int t0 = (blockIdx.x * 4 + warp) * 4;

    const float4* x0  = (const float4*)(x + (size_t)t0 * DIN);
    const float4* wr4 = (const float4*)Wr;

    float acc[4][NE];
#pragma unroll
    for (int tt = 0; tt < 4; tt++)
#pragma unroll
        for (int e = 0; e < NE; e++) acc[tt][e] = 0.f;

#pragma unroll 2
    for (int it = 0; it < 32; it++) {
        int idx = lane + 32 * it;
        float4 wv[NE];
#pragma unroll
        for (int e = 0; e < NE; e++) wv[e] = __ldg(&wr4[e * 1024 + idx]);
#pragma unroll
        for (int tt = 0; tt < 4; tt++) {
            float4 xv = __ldg(&x0[tt * 1024 + idx]);
#pragma unroll
            for (int e = 0; e < NE; e++)
                acc[tt][e] += xv.x * wv[e].x + xv.y * wv[e].y
                            + xv.z * wv[e].z + xv.w * wv[e].w;
            *(uint2*)(g_xh + (size_t)(t0 + tt) * DIN + idx * 4) =
                make_uint2(f2h2(xv.x, xv.y), f2h2(xv.z, xv.w));
        }
    }
#pragma unroll
    for (int tt = 0; tt < 4; tt++)
#pragma unroll
        for (int e = 0; e < NE; e++) {
            float v = acc[tt][e];
#pragma unroll
            for (int o = 16; o; o >>= 1) v += __shfl_xor_sync(0xffffffffu, v, o);
            acc[tt][e] = v;
        }

    if (lane == 0) {
#pragma unroll
        for (int tt = 0; tt < 4; tt++) {
            int t = t0 + tt;
            float l[NE];
            float m = -1e30f;
#pragma unroll
            for (int e = 0; e < NE; e++) { l[e] = acc[tt][e] + __ldg(&br[e]); m = fmaxf(m, l[e]); }
#pragma unroll
            for (int e = 0; e < NE; e++) l[e] = fminf(fmaxf(l[e] - m, -20.f), 20.f);

            int e0 = 0; float v0 = l[0];
#pragma unroll
            for (int e = 1; e < NE; e++) if (l[e] > v0) { v0 = l[e]; e0 = e; }
            int e1 = -1; float v1 = -1e30f;
#pragma unroll
            for (int e = 0; e < NE; e++) if (e != e0 && l[e] > v1) { v1 = l[e]; e1 = e; }

            float w1 = expf(v1 - v0);
            g_gate[2 * t]     = 1.f / (1.f + w1);
            g_gate[2 * t + 1] = w1 / (1.f + w1);

            int pr  = e0 * NE + e1;
            int pos = atomicAdd(&g_pairCount[pr], 1);
            g_pairList[pr * T_TOT + pos] = t;
        }
    }
}

// ---------------------------------------------------------------------------
// Compact: serial single-thread version (R9-proven).
__global__ void k_compact() {
    if (threadIdx.x == 0) {
        int nt = 0;
        for (int p = 0; p < NPAIR; p++) {
            int c = g_pairCount[p];
            for (int j = 0; j * TILE_T < c && nt < MAX_TILES; j++) {
                g_tilePair[nt] = p;
                g_tileOff[nt]  = p * T_TOT + j * TILE_T;
                int len = c - j * TILE_T;
                g_tileLen[nt]  = len < TILE_T ? len : TILE_T;
                nt++;
            }
        }
        g_numTiles = nt;
    }
}

// ---------------------------------------------------------------------------
// k_h: Hpart[split] = X * Acomb^T over k-range [split*1024, +1024).
// grid (MAX_TILES, KSPLIT), 256 threads (8 warps), warp tile m32 x n32,
// 3-stage cp.async (24KB/stage). smem 74.75KB -> 2 CTAs/SM.
#define HXS(s) (1024 + (s) * 24576)
#define HAS(s) (1024 + (s) * 24576 + 16384)
#define SMEM_H (1024 + 3 * 24576)           // 74752 B

__global__ __launch_bounds__(256, 2) void k_h()
{
    extern __shared__ char smem[];
    const u32 sb = s2u(smem);
    int tid  = threadIdx.x;
    int wid  = tid >> 5;
    int lane = tid & 31;

    int bid = blockIdx.x;
    if (bid >= g_numTiles) return;
    int split = blockIdx.y;

    int p   = g_tilePair[bid];
    int e0  = p >> 3, e1 = p & 7;
    int off = g_tileOff[bid], len = g_tileLen[bid];

    int* toks = (int*)smem;
    if (tid < TILE_T) toks[tid] = g_pairList[off + (tid < len ? tid : 0)];
    __syncthreads();

    int mgrp = wid & 3, ngrp = wid >> 2;
    int kbase = split * (DIN / KSPLIT);

    // cp.async mappings: X 1024 units (4/thread), A 512 units (2/thread)
    const __half* xsrc[4]; u32 xdst[4];
#pragma unroll
    for (int j = 0; j < 4; j++) {
        int u = tid + 256 * j;
        int r = u >> 3, pc = u & 7;
        xsrc[j] = g_xh + (size_t)toks[r] * DIN + kbase + pc * 8;
        xdst[j] = swz((u32)(r * 128 + pc * 16));
    }
    const __half* asrc[2]; u32 adst[2];
#pragma unroll
    for (int j = 0; j < 2; j++) {
        int u = tid + 256 * j;
        int r = u >> 3, pc = u & 7;
        int e = r < RK ? e0 : e1;
        asrc[j] = g_Ah + ((size_t)e * RK + (r & 31)) * DIN + kbase + pc * 8;
        adst[j] = swz((u32)(r * 128 + pc * 16));
    }

    auto issue = [&](int c) {
        int s = c % 3, k0 = c * KC;
#pragma unroll
        for (int j = 0; j < 4; j++) cpa16(sb + HXS(s) + xdst[j], xsrc[j] + k0);
#pragma unroll
        for (int j = 0; j < 2; j++) cpa16(sb + HAS(s) + adst[j], asrc[j] + k0);
        CPA_COMMIT();
    };

    float acc[2][4][4];
#pragma unroll
    for (int i = 0; i < 2; i++)
#pragma unroll
        for (int j = 0; j < 4; j++)
#pragma unroll
            for (int q = 0; q < 4; q++) acc[i][j][q] = 0.f;

    issue(0); issue(1);
    for (int c = 0; c < DIN / KSPLIT / KC; c++) {     // 16 chunks
        if (c + 2 < DIN / KSPLIT / KC) issue(c + 2);
        else CPA_COMMIT();          // empty group: keeps wait_group accounting
        CPA_WAIT(2);
        __syncthreads();

        int s = c % 3;
#pragma unroll
        for (int ks = 0; ks < 4; ks++) {
            u32 xf[2][4];
#pragma unroll
            for (int mt = 0; mt < 2; mt++) {
                u32 ro = (u32)((mgrp * 32 + mt * 16 + (lane & 15)) * 128
                               + ks * 32 + (lane >> 4) * 16);
                ldsm4(xf[mt], sb + HXS(s) + swz(ro));
            }
            u32 af[8];
#pragma unroll
            for (int g = 0; g < 2; g++) {
                u32 ro = (u32)((ngrp * 32 + g * 16 + ((lane >> 4) << 3) + (lane & 7)) * 128
                               + ks * 32 + ((lane >> 3) & 1) * 16);
                ldsm4(af + 4 * g, sb + HAS(s) + swz(ro));
            }
#pragma unroll
            for (int mt = 0; mt < 2; mt++)
#pragma unroll
                for (int nt = 0; nt < 4; nt++)
                    mma16816(acc[mt][nt], xf[mt], af[2 * nt], af[2 * nt + 1]);
        }
        __syncthreads();
    }
    CPA_WAIT(0);

    // write fp32 partials
    float* hp = g_Hpart + ((size_t)(split * MAX_TILES + bid)) * (TILE_T * 64);
#pragma unroll
    for (int mt = 0; mt < 2; mt++) {
        int r0 = mgrp * 32 + mt * 16 + (lane >> 2);
#pragma unroll
        for (int nt = 0; nt < 4; nt++) {
            float* d = acc[mt][nt];
            int c0 = ngrp * 32 + nt * 8 + 2 * (lane & 3);
            *(float2*)(hp + r0 * 64 + c0)       = make_float2(d[0], d[1]);
            *(float2*)(hp + (r0 + 8) * 64 + c0) = make_float2(d[2], d[3]);
        }
    }
}

// ---------------------------------------------------------------------------
// k_out: out = (gate * sum_splits Hpart) * Bcomb^T over n-range
// [blockIdx.y*2048, +2048). grid (MAX_TILES, 2), 256 threads (8 warps),
// warp rows wid*16..+15, 2-stage cp.async B (32KB/stage). smem 82.9KB.
#define OH_OFF 1024
#define OBS(s) (1024 + 16384 + (s) * 32768)
#define SMEM_O (1024 + 16384 + 2 * 32768)   // 82944 B

__global__ __launch_bounds__(256, 2) void k_out(float* __restrict__ out)
{
    extern __shared__ char smem[];
    const u32 sb = s2u(smem);
    int tid  = threadIdx.x;
    int wid  = tid >> 5;
    int lane = tid & 31;

    int bid = blockIdx.x;
    if (bid >= g_numTiles) return;
    int ybase = blockIdx.y * (DOUT / 2);

    int p   = g_tilePair[bid];
    int e0  = p >> 3, e1 = p & 7;
    int off = g_tileOff[bid], len = g_tileLen[bid];

    int* toks = (int*)smem;
    if (tid < TILE_T) toks[tid] = g_pairList[off + (tid < len ? tid : 0)];
    __syncthreads();

    // ---- prologue: sum 4 partials, gate, fp16 -> smem H (SW128 rows) ----
    {
        int row  = tid >> 1;
        int half = tid & 1;
        int tok  = toks[row];
        float g  = g_gate[2 * tok + half];
        const float* hp = g_Hpart + (size_t)bid * (TILE_T * 64) + row * 64 + half * 32;
        const size_t sstr = (size_t)MAX_TILES * TILE_T * 64;
#pragma unroll
        for (int j = 0; j < 8; j++) {
            float4 v = *(const float4*)(hp + j * 4);
#pragma unroll
            for (int s = 1; s < KSPLIT; s++) {
                float4 w = *(const float4*)(hp + s * sstr + j * 4);
                v.x += w.x; v.y += w.y; v.z += w.z; v.w += w.w;
            }
            v.x *= g; v.y *= g; v.z *= g; v.w *= g;
            u32 so = swz((u32)(row * 128 + half * 64 + j * 8));
            sts32(sb + OH_OFF + so,     f2h2(v.x, v.y));
            sts32(sb + OH_OFF + so + 4, f2h2(v.z, v.w));
        }
    }

    // B cp.async mapping: 8 units/thread per chunk
    const __half* bsrc[8]; u32 bdst[8];
#pragma unroll
    for (int j = 0; j < 8; j++) {
        int u = tid + 256 * j;
        int n = u >> 3, pc = u & 7;
        int e = pc < 4 ? e0 : e1;
        bsrc[j] = g_Bh + ((size_t)e * DOUT + ybase + n) * RK + (pc & 3) * 8;
        bdst[j] = swz((u32)(n * 128 + pc * 16));
    }
    auto issue = [&](int c) {
        int s = c & 1;
        size_t koff = (size_t)c * NC * RK;
#pragma unroll
        for (int j = 0; j < 8; j++) cpa16(sb + OBS(s) + bdst[j], bsrc[j] + koff);
        CPA_COMMIT();
    };

    issue(0);
    __syncthreads();        // H smem ready (also covers first B stage ordering)

    u32 Hf[4][4];
#pragma unroll
    for (int ks = 0; ks < 4; ks++) {
        u32 ro = (u32)((wid * 16 + (lane & 15)) * 128 + ks * 32 + (lane >> 4) * 16);
        ldsm4(Hf[ks], sb + OH_OFF + swz(ro));
    }

    int r0   = wid * 16 + (lane >> 2);
    bool lv0 = r0 < len, lv1 = (r0 + 8) < len;
    size_t orow0 = (size_t)toks[r0] * DOUT + ybase;
    size_t orow1 = (size_t)toks[r0 + 8] * DOUT + ybase;

    for (int c = 0; c < DOUT / 2 / NC; c++) {        // 8 chunks
        if (c + 1 < DOUT / 2 / NC) issue(c + 1);
        else CPA_COMMIT();          // empty group: keeps wait_group accounting
        CPA_WAIT(1);
        __syncthreads();

        int s = c & 1;
#pragma unroll
        for (int nsub = 0; nsub < 4; nsub++) {
            float a2[8][4];
#pragma unroll
            for (int j = 0; j < 8; j++)
#pragma unroll
                for (int q = 0; q < 4; q++) a2[j][q] = 0.f;

#pragma unroll
            for (int ks = 0; ks < 4; ks++) {
                u32 bf[16];
#pragma unroll
                for (int g = 0; g < 4; g++) {
                    u32 ro = (u32)((nsub * 64 + g * 16 + ((lane >> 4) << 3) + (lane & 7)) * 128
                                   + ks * 32 + ((lane >> 3) & 1) * 16);
                    ldsm4(bf + 4 * g, sb + OBS(s) + swz(ro));
                }
#pragma unroll
                for (int nt = 0; nt < 8; nt++)
                    mma16816(a2[nt], Hf[ks], bf[2 * nt], bf[2 * nt + 1]);
            }
            size_t ob = (size_t)(c * NC + nsub * 64 + 2 * (lane & 3));
#pragma unroll
            for (int nt = 0; nt < 8; nt++) {
                if (lv0) *(float2*)(out + orow0 + ob + nt * 8) = make_float2(a2[nt][0], a2[nt][1]);
                if (lv1) *(float2*)(out + orow1 + ob + nt * 8) = make_float2(a2[nt][2], a2[nt][3]);
            }
        }
        __syncthreads();
    }
    CPA_WAIT(0);
}

// ---------------------------------------------------------------------------
extern "C" void kernel_launch(void* const* d_in, const int* in_sizes, int n_in,
                              void* d_out, int out_size)
{
    (void)in_sizes; (void)n_in; (void)out_size;
    const float* x  = (const float*)d_in[0];
    const float* A  = (const float*)d_in[1];
    const float* Bw = (const float*)d_in[2];
    const float* Wr = (const float*)d_in[3];
    const float* br = (const float*)d_in[4];
    float* out = (float*)d_out;

    cudaFuncSetAttribute(k_h,   cudaFuncAttributeMaxDynamicSharedMemorySize, SMEM_H);
    cudaFuncSetAttribute(k_out, cudaFuncAttributeMaxDynamicSharedMemorySize, SMEM_O);

    k_prep<<<2048, 256>>>(A, Bw);
    k_router<<<T_TOT / 16, 128>>>(x, Wr, br);
    k_compact<<<1, 32>>>();
    k_h<<<dim3(MAX_TILES, KSPLIT), 256, SMEM_H>>>();
    k_out<<<dim3(MAX_TILES, 2), 256, SMEM_O>>>(out);
}